// round 14
// baseline (speedup 1.0000x reference)
#include <cuda_runtime.h>
#include <math.h>
#include <stdint.h>

#define D_MODEL 1024
#define NUM_HEADS 16
#define DK 64
#define BATCH 2
#define SEQ 2048
#define M_TOTAL (BATCH * SEQ)  // 4096

// GEMM smem geometry (4-stage cp.async)
#define A_ROW_STRIDE 20
#define A_STAGE_WORDS (128 * A_ROW_STRIDE)
#define B0_STAGE_WORDS (16 * 136)
#define B1_STAGE_WORDS (128 * A_ROW_STRIDE)
#define NSTAGE 4

// flash smem strides:
//  K: LDS.64 at gid*KRS + kk*8 + 2*tig -> KRS%32==8 -> 72 (cols pre-permuted in g_k)
//  V: LDS.32 at tig*VRS + gid          -> VRS%32==8 -> 72
#define KRS 72
#define VRS 72
#define KB_WORDS (64 * KRS)     // 4608 per buffer
#define VB_WORDS (64 * VRS)     // 4608 per buffer

__device__ float g_q[BATCH * NUM_HEADS * SEQ * DK];   // natural
__device__ float g_k[BATCH * NUM_HEADS * SEQ * DK];   // cols pair-permuted within 8-groups
__device__ float g_v[BATCH * NUM_HEADS * SEQ * DK];   // natural
__device__ float g_cat[M_TOTAL * D_MODEL];

__device__ __forceinline__ uint32_t f2tf(float f) {
    uint32_t u;
    asm("cvt.rna.tf32.f32 %0, %1;" : "=r"(u) : "f"(f));
    return u;
}

__device__ __forceinline__ void mma_tf32(float* c, const uint32_t* a, const uint32_t* b) {
    asm volatile(
        "mma.sync.aligned.m16n8k8.row.col.f32.tf32.tf32.f32 "
        "{%0,%1,%2,%3}, {%4,%5,%6,%7}, {%8,%9}, {%0,%1,%2,%3};"
        : "+f"(c[0]), "+f"(c[1]), "+f"(c[2]), "+f"(c[3])
        : "r"(a[0]), "r"(a[1]), "r"(a[2]), "r"(a[3]), "r"(b[0]), "r"(b[1]));
}
__device__ __forceinline__ void mma_tf32_v(float* c, const uint32_t* a, uint32_t b0, uint32_t b1) {
    asm volatile(
        "mma.sync.aligned.m16n8k8.row.col.f32.tf32.tf32.f32 "
        "{%0,%1,%2,%3}, {%4,%5,%6,%7}, {%8,%9}, {%0,%1,%2,%3};"
        : "+f"(c[0]), "+f"(c[1]), "+f"(c[2]), "+f"(c[3])
        : "r"(a[0]), "r"(a[1]), "r"(a[2]), "r"(a[3]), "r"(b0), "r"(b1));
}

__device__ __forceinline__ void cpa16(uint32_t* smem_dst, const float* gsrc) {
    uint32_t s = (uint32_t)__cvta_generic_to_shared(smem_dst);
    asm volatile("cp.async.cg.shared.global [%0], [%1], 16;" :: "r"(s), "l"(gsrc));
}
__device__ __forceinline__ void cpa_commit() {
    asm volatile("cp.async.commit_group;");
}
template <int N>
__device__ __forceinline__ void cpa_wait() {
    asm volatile("cp.async.wait_group %0;" :: "n"(N));
}

// =====================================================================
// Out-projection GEMM (R7-R9 template, known-good): NSTAGE=4, one
// sync per k-chunk. MODE 1: out[m,n] = X @ Wo[n,:]^T + bo
// =====================================================================
template <int MODE>
__global__ __launch_bounds__(256, 2) void gemm_v3_kernel(
    const float* __restrict__ X, const float* __restrict__ W,
    const float* __restrict__ bias, float* __restrict__ out)
{
    extern __shared__ uint32_t sg[];
    uint32_t* smA = sg;
    uint32_t* smB = sg + NSTAGE * A_STAGE_WORDS;
    const int BSTW = (MODE == 0) ? B0_STAGE_WORDS : B1_STAGE_WORDS;

    const int t    = threadIdx.x;
    const int n0   = blockIdx.x * 128;
    const int m0   = blockIdx.y * 128;
    const int warp = t >> 5;
    const int lane = t & 31;
    const int gid  = lane >> 2;
    const int tig  = lane & 3;
    const int wm   = (warp & 1) * 64;
    const int wn   = (warp >> 1) * 32;

    const int am[2] = { (t + 0) >> 2, (t + 256) >> 2 };
    const int ak4   = (t & 3) << 2;

    float acc[4][4][4];
#pragma unroll
    for (int i = 0; i < 4; i++)
#pragma unroll
        for (int j = 0; j < 4; j++)
#pragma unroll
            for (int k = 0; k < 4; k++) acc[i][j][k] = 0.f;

    auto issue = [&](int stage, int kc) {
        uint32_t* As_ = smA + stage * A_STAGE_WORDS;
        uint32_t* Bs_ = smB + stage * BSTW;
#pragma unroll
        for (int rep = 0; rep < 2; rep++) {
            int m = am[rep];
            cpa16(As_ + m * A_ROW_STRIDE + ak4,
                  X + (size_t)(m0 + m) * D_MODEL + kc * 16 + ak4);
        }
#pragma unroll
        for (int rep = 0; rep < 2; rep++) {
            int f = t + rep * 256;
            if (MODE == 0) {
                int k = f >> 5, n4 = (f & 31) << 2;
                int bn = n0 + n4;
                int ck = ((k >> 2) & 3) << 2;
                cpa16(Bs_ + k * 136 + (n4 ^ ck),
                      W + (size_t)(bn >> 6) * (D_MODEL * DK)
                        + (size_t)(kc * 16 + k) * DK + (bn & 63));
            } else {
                int n = f >> 2, k4 = (f & 3) << 2;
                cpa16(Bs_ + n * A_ROW_STRIDE + k4,
                      W + (size_t)(n0 + n) * D_MODEL + kc * 16 + k4);
            }
        }
    };

    auto compute = [&](int stage) {
        uint32_t* As_ = smA + stage * A_STAGE_WORDS;
        uint32_t* Bs_ = smB + stage * BSTW;
#pragma unroll
        for (int ks = 0; ks < 2; ks++) {
            const int kb = ks * 8;
            uint32_t af[4][4];
#pragma unroll
            for (int mt = 0; mt < 4; mt++) {
                const int r = (wm + mt * 16 + gid) * A_ROW_STRIDE;
                af[mt][0] = As_[r + kb + tig];
                af[mt][1] = As_[r + 8 * A_ROW_STRIDE + kb + tig];
                af[mt][2] = As_[r + kb + tig + 4];
                af[mt][3] = As_[r + 8 * A_ROW_STRIDE + kb + tig + 4];
            }
            uint32_t bf[4][2];
#pragma unroll
            for (int nt = 0; nt < 4; nt++) {
                const int ncol = wn + nt * 8 + gid;
                if (MODE == 0) {
                    const int x0 = ks ? 8 : 0;
                    const int x1 = ks ? 12 : 4;
                    bf[nt][0] = Bs_[(kb + tig) * 136 + (ncol ^ x0)];
                    bf[nt][1] = Bs_[(kb + tig + 4) * 136 + (ncol ^ x1)];
                } else {
                    bf[nt][0] = Bs_[ncol * A_ROW_STRIDE + kb + tig];
                    bf[nt][1] = Bs_[ncol * A_ROW_STRIDE + kb + tig + 4];
                }
            }
#pragma unroll
            for (int mt = 0; mt < 4; mt++)
#pragma unroll
                for (int nt = 0; nt < 4; nt++) mma_tf32(acc[mt][nt], af[mt], bf[nt]);
        }
    };

    issue(0, 0); cpa_commit();
    issue(1, 1); cpa_commit();
    issue(2, 2); cpa_commit();
    for (int kc = 0; kc < 64; kc++) {
        cpa_wait<2>();
        __syncthreads();
        compute(kc & 3);
        if (kc + 3 < 64) issue((kc + 3) & 3, kc + 3);
        cpa_commit();
    }

#pragma unroll
    for (int mt = 0; mt < 4; mt++) {
#pragma unroll
        for (int nt = 0; nt < 4; nt++) {
            const int r0 = m0 + wm + mt * 16 + gid;
            const int r1 = r0 + 8;
            const int c  = n0 + wn + nt * 8 + tig * 2;
            const float bv0 = bias[c], bv1 = bias[c + 1];
            float2 v0 = make_float2(acc[mt][nt][0] + bv0, acc[mt][nt][1] + bv1);
            float2 v1 = make_float2(acc[mt][nt][2] + bv0, acc[mt][nt][3] + bv1);
            if (MODE == 0) {
                const int h = c >> 6, kd = c & 63;
                const int b0_ = r0 >> 11, s0 = r0 & 2047;
                const int b1_ = r1 >> 11, s1 = r1 & 2047;
                *(float2*)(out + (((size_t)b0_ * NUM_HEADS + h) * SEQ + s0) * DK + kd) = v0;
                *(float2*)(out + (((size_t)b1_ * NUM_HEADS + h) * SEQ + s1) * DK + kd) = v1;
            } else {
                *(float2*)(out + (size_t)r0 * D_MODEL + c) = v0;
                *(float2*)(out + (size_t)r1 * D_MODEL + c) = v1;
            }
        }
    }
}

// =====================================================================
// Proj GEMM v3 (R9 arithmetic EXACTLY — no scaling) + K-only column
// pair-permutation in the epilogue: for z==1, element d stored at
// (d&~7)|((d&3)*2+(d>>2)). Values unchanged, positions only.
// =====================================================================
struct ProjArgs {
    const float* X[3];
    const float* W[3];
    const float* bias[3];
    float* out[3];
};

__global__ __launch_bounds__(256, 2) void proj_gemm3_v3_kernel(ProjArgs args)
{
    extern __shared__ uint32_t sg[];
    const int z = blockIdx.z;
    const float* X    = args.X[z];
    const float* W    = args.W[z];
    const float* bias = args.bias[z];
    float* out        = args.out[z];
    const bool kperm  = (z == 1);

    uint32_t* smA = sg;
    uint32_t* smB = sg + NSTAGE * A_STAGE_WORDS;

    const int t    = threadIdx.x;
    const int n0   = blockIdx.x * 128;
    const int m0   = blockIdx.y * 128;
    const int warp = t >> 5;
    const int lane = t & 31;
    const int gid  = lane >> 2;
    const int tig  = lane & 3;
    const int wm   = (warp & 1) * 64;
    const int wn   = (warp >> 1) * 32;

    const int am[2] = { (t + 0) >> 2, (t + 256) >> 2 };
    const int ak4   = (t & 3) << 2;

    float acc[4][4][4];
#pragma unroll
    for (int i = 0; i < 4; i++)
#pragma unroll
        for (int j = 0; j < 4; j++)
#pragma unroll
            for (int k = 0; k < 4; k++) acc[i][j][k] = 0.f;

    auto issue = [&](int stage, int kc) {
        uint32_t* As_ = smA + stage * A_STAGE_WORDS;
        uint32_t* Bs_ = smB + stage * B0_STAGE_WORDS;
#pragma unroll
        for (int rep = 0; rep < 2; rep++) {
            int m = am[rep];
            cpa16(As_ + m * A_ROW_STRIDE + ak4,
                  X + (size_t)(m0 + m) * D_MODEL + kc * 16 + ak4);
        }
#pragma unroll
        for (int rep = 0; rep < 2; rep++) {
            int f = t + rep * 256;
            int k = f >> 5, n4 = (f & 31) << 2;
            int bn = n0 + n4;
            int ck = ((k >> 2) & 3) << 2;
            cpa16(Bs_ + k * 136 + (n4 ^ ck),
                  W + (size_t)(bn >> 6) * (D_MODEL * DK)
                    + (size_t)(kc * 16 + k) * DK + (bn & 63));
        }
    };

    auto compute = [&](int stage) {
        uint32_t* As_ = smA + stage * A_STAGE_WORDS;
        uint32_t* Bs_ = smB + stage * B0_STAGE_WORDS;
#pragma unroll
        for (int ks = 0; ks < 2; ks++) {
            const int kb = ks * 8;
            const int x0 = ks ? 8 : 0;
            const int x1 = ks ? 12 : 4;
            uint32_t af[4][4];
#pragma unroll
            for (int mt = 0; mt < 4; mt++) {
                const int r = (wm + mt * 16 + gid) * A_ROW_STRIDE;
                af[mt][0] = As_[r + kb + tig];
                af[mt][1] = As_[r + 8 * A_ROW_STRIDE + kb + tig];
                af[mt][2] = As_[r + kb + tig + 4];
                af[mt][3] = As_[r + 8 * A_ROW_STRIDE + kb + tig + 4];
            }
            uint32_t bf[4][2];
#pragma unroll
            for (int nt = 0; nt < 4; nt++) {
                const int ncol = wn + nt * 8 + gid;
                bf[nt][0] = Bs_[(kb + tig) * 136 + (ncol ^ x0)];
                bf[nt][1] = Bs_[(kb + tig + 4) * 136 + (ncol ^ x1)];
            }
#pragma unroll
            for (int mt = 0; mt < 4; mt++)
#pragma unroll
                for (int nt = 0; nt < 4; nt++) mma_tf32(acc[mt][nt], af[mt], bf[nt]);
        }
    };

    issue(0, 0); cpa_commit();
    issue(1, 1); cpa_commit();
    issue(2, 2); cpa_commit();
    for (int kc = 0; kc < 64; kc++) {
        cpa_wait<2>();
        __syncthreads();
        compute(kc & 3);
        if (kc + 3 < 64) issue((kc + 3) & 3, kc + 3);
        cpa_commit();
    }

#pragma unroll
    for (int mt = 0; mt < 4; mt++) {
#pragma unroll
        for (int nt = 0; nt < 4; nt++) {
            const int r0 = m0 + wm + mt * 16 + gid;
            const int r1 = r0 + 8;
            const int c  = n0 + wn + nt * 8 + tig * 2;
            const float bv0 = bias[c], bv1 = bias[c + 1];
            float va = acc[mt][nt][0] + bv0;
            float vb = acc[mt][nt][1] + bv1;
            float vc = acc[mt][nt][2] + bv0;
            float vd = acc[mt][nt][3] + bv1;
            const int h = c >> 6, kd = c & 63;
            const int b0_ = r0 >> 11, s0 = r0 & 2047;
            const int b1_ = r1 >> 11, s1 = r1 & 2047;
            float* p0 = out + (((size_t)b0_ * NUM_HEADS + h) * SEQ + s0) * DK;
            float* p1 = out + (((size_t)b1_ * NUM_HEADS + h) * SEQ + s1) * DK;
            if (kperm) {
                const int g8 = kd & ~7;
                const int d0 = kd & 7, d1 = d0 + 1;
                const int q0_ = g8 + ((d0 & 3) * 2 + (d0 >> 2));
                const int q1_ = g8 + ((d1 & 3) * 2 + (d1 >> 2));
                p0[q0_] = va;  p0[q1_] = vb;
                p1[q0_] = vc;  p1[q1_] = vd;
            } else {
                *(float2*)(p0 + kd) = make_float2(va, vb);
                *(float2*)(p1 + kd) = make_float2(vc, vd);
            }
        }
    }
}

// =====================================================================
// Flash attention v9b: R9 skeleton (flash scales Q by 0.125 itself);
// K rows permuted at copy AND K columns pre-permuted in g_k, so the
// S-phase B-fragment is a single conflict-free LDS.64 (KRS=72).
// Register-resident P; 16B cp.async double-buffered K/V.
// =====================================================================
__global__ __launch_bounds__(256, 2) void flash_mma_kernel()
{
    extern __shared__ uint32_t smu[];
    uint32_t* KsB = smu;                  // 2 x [64][KRS]
    uint32_t* VsB = smu + 2 * KB_WORDS;   // 2 x [64][VRS]

    const int t    = threadIdx.x;
    const int warp = t >> 5;
    const int lane = t & 31;
    const int gid  = lane >> 2;
    const int tig  = lane & 3;
    const int q0   = blockIdx.x * 128;
    const int bh   = blockIdx.y;

    const float* qb = g_q + (size_t)bh * SEQ * DK;
    const float* kb = g_k + (size_t)bh * SEQ * DK;
    const float* vb = g_v + (size_t)bh * SEQ * DK;

    const int r0 = q0 + warp * 16 + gid;
    const int r1 = r0 + 8;
    uint32_t qf[8][4];
#pragma unroll
    for (int kk = 0; kk < 8; kk++) {
        qf[kk][0] = f2tf(qb[(size_t)r0 * DK + kk * 8 + tig]     * 0.125f);
        qf[kk][1] = f2tf(qb[(size_t)r1 * DK + kk * 8 + tig]     * 0.125f);
        qf[kk][2] = f2tf(qb[(size_t)r0 * DK + kk * 8 + tig + 4] * 0.125f);
        qf[kk][3] = f2tf(qb[(size_t)r1 * DK + kk * 8 + tig + 4] * 0.125f);
    }

    float m0 = -INFINITY, m1 = -INFINITY, l0 = 0.f, l1 = 0.f;
    float o[8][4];
#pragma unroll
    for (int j = 0; j < 8; j++)
#pragma unroll
        for (int k = 0; k < 4; k++) o[j][k] = 0.f;

    const int crow[4] = { (t + 0) >> 4, (t + 256) >> 4, (t + 512) >> 4, (t + 768) >> 4 };
    const int cc4     = (t & 15) << 2;

    auto issue_kv = [&](int buf, int s0) {
        uint32_t* Ks_ = KsB + buf * KB_WORDS;
        uint32_t* Vs_ = VsB + buf * VB_WORDS;
#pragma unroll
        for (int rep = 0; rep < 4; rep++) {
            int row  = crow[rep];
            int prow = (row & ~7) | ((row & 3) << 1) | ((row >> 2) & 1);
            cpa16(Ks_ + prow * KRS + cc4, kb + (size_t)(s0 + row) * DK + cc4);
            cpa16(Vs_ + row  * VRS + cc4, vb + (size_t)(s0 + row) * DK + cc4);
        }
        cpa_commit();
    };

    issue_kv(0, 0);

    for (int tile = 0; tile < SEQ / 64; tile++) {
        const int buf = tile & 1;
        uint32_t* Ks = KsB + buf * KB_WORDS;
        uint32_t* Vs = VsB + buf * VB_WORDS;

        cpa_wait<0>();
        __syncthreads();
        if (tile + 1 < SEQ / 64) issue_kv(buf ^ 1, (tile + 1) * 64);

        // ---- S = Q K^T : B-fragment = one LDS.64 (cols pre-permuted) ----
        float sacc[8][4];
#pragma unroll
        for (int j = 0; j < 8; j++)
#pragma unroll
            for (int k = 0; k < 4; k++) sacc[j][k] = 0.f;
#pragma unroll
        for (int kk = 0; kk < 8; kk++) {
#pragma unroll
            for (int j = 0; j < 8; j++) {
                uint2 b = *(const uint2*)&Ks[(j * 8 + gid) * KRS + kk * 8 + 2 * tig];
                mma_tf32_v(sacc[j], qf[kk], b.x, b.y);
            }
        }

        // ---- fragment-resident online softmax ----
        float t0 = -INFINITY, t1 = -INFINITY;
#pragma unroll
        for (int j = 0; j < 8; j++) {
            t0 = fmaxf(t0, fmaxf(sacc[j][0], sacc[j][1]));
            t1 = fmaxf(t1, fmaxf(sacc[j][2], sacc[j][3]));
        }
        t0 = fmaxf(t0, __shfl_xor_sync(0xffffffffu, t0, 1));
        t0 = fmaxf(t0, __shfl_xor_sync(0xffffffffu, t0, 2));
        t1 = fmaxf(t1, __shfl_xor_sync(0xffffffffu, t1, 1));
        t1 = fmaxf(t1, __shfl_xor_sync(0xffffffffu, t1, 2));

        float nm0 = fmaxf(m0, t0), nm1 = fmaxf(m1, t1);
        float a0 = __expf(m0 - nm0), a1 = __expf(m1 - nm1);
        m0 = nm0; m1 = nm1;

        float p0 = 0.f, p1 = 0.f;
#pragma unroll
        for (int j = 0; j < 8; j++) {
            float e0 = __expf(sacc[j][0] - nm0);
            float e1 = __expf(sacc[j][1] - nm0);
            float e2 = __expf(sacc[j][2] - nm1);
            float e3 = __expf(sacc[j][3] - nm1);
            p0 += e0 + e1;
            p1 += e2 + e3;
            sacc[j][0] = __uint_as_float(f2tf(e0));
            sacc[j][1] = __uint_as_float(f2tf(e1));
            sacc[j][2] = __uint_as_float(f2tf(e2));
            sacc[j][3] = __uint_as_float(f2tf(e3));
        }
        p0 += __shfl_xor_sync(0xffffffffu, p0, 1);
        p0 += __shfl_xor_sync(0xffffffffu, p0, 2);
        p1 += __shfl_xor_sync(0xffffffffu, p1, 1);
        p1 += __shfl_xor_sync(0xffffffffu, p1, 2);
        l0 = l0 * a0 + p0;
        l1 = l1 * a1 + p1;

#pragma unroll
        for (int j = 0; j < 8; j++) {
            o[j][0] *= a0; o[j][1] *= a0;
            o[j][2] *= a1; o[j][3] *= a1;
        }

        // ---- O += P V (P in registers, A-frag order {e0,e2,e1,e3}) ----
#pragma unroll
        for (int kk = 0; kk < 8; kk++) {
            uint32_t af[4];
            af[0] = __float_as_uint(sacc[kk][0]);
            af[1] = __float_as_uint(sacc[kk][2]);
            af[2] = __float_as_uint(sacc[kk][1]);
            af[3] = __float_as_uint(sacc[kk][3]);
#pragma unroll
            for (int j = 0; j < 8; j++) {
                uint32_t bf[2];
                bf[0] = Vs[(kk * 8 + tig) * VRS + j * 8 + gid];
                bf[1] = Vs[(kk * 8 + tig + 4) * VRS + j * 8 + gid];
                mma_tf32(o[j], af, bf);
            }
        }
    }

    const float i0 = 1.f / l0, i1 = 1.f / l1;
    const int b_ = bh >> 4, h = bh & 15;
    float* row0 = g_cat + (size_t)(b_ * SEQ + r0) * D_MODEL + h * DK;
    float* row1 = g_cat + (size_t)(b_ * SEQ + r1) * D_MODEL + h * DK;
#pragma unroll
    for (int j = 0; j < 8; j++) {
        *(float2*)(row0 + j * 8 + tig * 2) = make_float2(o[j][0] * i0, o[j][1] * i0);
        *(float2*)(row1 + j * 8 + tig * 2) = make_float2(o[j][2] * i1, o[j][3] * i1);
    }
}

extern "C" void kernel_launch(void* const* d_in, const int* in_sizes, int n_in,
                              void* d_out, int out_size)
{
    const float* Q  = (const float*)d_in[0];
    const float* K  = (const float*)d_in[1];
    const float* V  = (const float*)d_in[2];
    const float* Wq = (const float*)d_in[3];
    const float* bq = (const float*)d_in[4];
    const float* Wk = (const float*)d_in[5];
    const float* bk = (const float*)d_in[6];
    const float* Wv = (const float*)d_in[7];
    const float* bv = (const float*)d_in[8];
    const float* Wo = (const float*)d_in[9];
    const float* bo = (const float*)d_in[10];
    float* out = (float*)d_out;

    float *gq, *gk, *gv, *gcat;
    cudaGetSymbolAddress((void**)&gq, g_q);
    cudaGetSymbolAddress((void**)&gk, g_k);
    cudaGetSymbolAddress((void**)&gv, g_v);
    cudaGetSymbolAddress((void**)&gcat, g_cat);

    const int proj_smem  = (NSTAGE * A_STAGE_WORDS + NSTAGE * B0_STAGE_WORDS) * 4; // 75776
    const int outg_smem  = (NSTAGE * A_STAGE_WORDS + NSTAGE * B1_STAGE_WORDS) * 4; // 81920
    const int flash_smem = (2 * KB_WORDS + 2 * VB_WORDS) * 4;                      // 73728

    cudaFuncSetAttribute(proj_gemm3_v3_kernel,
                         cudaFuncAttributeMaxDynamicSharedMemorySize, proj_smem);
    cudaFuncSetAttribute(gemm_v3_kernel<1>,
                         cudaFuncAttributeMaxDynamicSharedMemorySize, outg_smem);
    cudaFuncSetAttribute(flash_mma_kernel,
                         cudaFuncAttributeMaxDynamicSharedMemorySize, flash_smem);

    ProjArgs pa;
    pa.X[0] = Q;  pa.X[1] = K;  pa.X[2] = V;
    pa.W[0] = Wq; pa.W[1] = Wk; pa.W[2] = Wv;
    pa.bias[0] = bq; pa.bias[1] = bk; pa.bias[2] = bv;
    pa.out[0] = gq; pa.out[1] = gk; pa.out[2] = gv;

    dim3 pgrd(D_MODEL / 128, M_TOTAL / 128, 3);
    proj_gemm3_v3_kernel<<<pgrd, dim3(256), proj_smem>>>(pa);

    dim3 fgrd(SEQ / 128, BATCH * NUM_HEADS);
    flash_mma_kernel<<<fgrd, dim3(256), flash_smem>>>();

    dim3 ogrd(D_MODEL / 128, M_TOTAL / 128);
    gemm_v3_kernel<1><<<ogrd, dim3(256), outg_smem>>>(gcat, Wo, bo, out);
}

// round 15
// speedup vs baseline: 1.0274x; 1.0274x over previous
#include <cuda_runtime.h>
#include <math.h>
#include <stdint.h>

#define D_MODEL 1024
#define NUM_HEADS 16
#define DK 64
#define BATCH 2
#define SEQ 2048
#define M_TOTAL (BATCH * SEQ)  // 4096

// GEMM smem geometry (4-stage cp.async)
#define A_ROW_STRIDE 20
#define A_STAGE_WORDS (128 * A_ROW_STRIDE)
#define B0_STAGE_WORDS (16 * 136)
#define B1_STAGE_WORDS (128 * A_ROW_STRIDE)
#define NSTAGE 4

// flash smem strides (R9, known-good): K/P loads gid*stride+tig -> stride%32==4;
// V loads tig*stride+gid -> stride%32==8.
#define KRS 68
#define VRS 72
#define KB_WORDS (64 * KRS)     // 4352 per buffer
#define VB_WORDS (64 * VRS)     // 4608 per buffer

__device__ float g_q[BATCH * NUM_HEADS * SEQ * DK];
__device__ float g_k[BATCH * NUM_HEADS * SEQ * DK];
__device__ float g_v[BATCH * NUM_HEADS * SEQ * DK];
__device__ float g_cat[M_TOTAL * D_MODEL];

__device__ __forceinline__ uint32_t f2tf(float f) {
    uint32_t u;
    asm("cvt.rna.tf32.f32 %0, %1;" : "=r"(u) : "f"(f));
    return u;
}

__device__ __forceinline__ void mma_tf32(float* c, const uint32_t* a, const uint32_t* b) {
    asm volatile(
        "mma.sync.aligned.m16n8k8.row.col.f32.tf32.tf32.f32 "
        "{%0,%1,%2,%3}, {%4,%5,%6,%7}, {%8,%9}, {%0,%1,%2,%3};"
        : "+f"(c[0]), "+f"(c[1]), "+f"(c[2]), "+f"(c[3])
        : "r"(a[0]), "r"(a[1]), "r"(a[2]), "r"(a[3]), "r"(b[0]), "r"(b[1]));
}

__device__ __forceinline__ void cpa16(uint32_t* smem_dst, const float* gsrc) {
    uint32_t s = (uint32_t)__cvta_generic_to_shared(smem_dst);
    asm volatile("cp.async.cg.shared.global [%0], [%1], 16;" :: "r"(s), "l"(gsrc));
}
__device__ __forceinline__ void cpa_commit() {
    asm volatile("cp.async.commit_group;");
}
template <int N>
__device__ __forceinline__ void cpa_wait() {
    asm volatile("cp.async.wait_group %0;" :: "n"(N));
}

// =====================================================================
// TF32 GEMM (R7-R9, known-good): cp.async 4-stage, ONE sync per k-chunk.
// MODE 0 (proj): out[b,h,s,kd] = X @ W[h] + bias
// MODE 1 (out):  out[m,n] = X @ Wo[n,:]^T + bo
// =====================================================================
template <int MODE>
__global__ __launch_bounds__(256, 2) void gemm_v3_kernel(
    const float* __restrict__ X, const float* __restrict__ W,
    const float* __restrict__ bias, float* __restrict__ out)
{
    extern __shared__ uint32_t sg[];
    uint32_t* smA = sg;
    uint32_t* smB = sg + NSTAGE * A_STAGE_WORDS;
    const int BSTW = (MODE == 0) ? B0_STAGE_WORDS : B1_STAGE_WORDS;

    const int t    = threadIdx.x;
    const int n0   = blockIdx.x * 128;
    const int m0   = blockIdx.y * 128;
    const int warp = t >> 5;
    const int lane = t & 31;
    const int gid  = lane >> 2;
    const int tig  = lane & 3;
    const int wm   = (warp & 1) * 64;
    const int wn   = (warp >> 1) * 32;

    const int am[2] = { (t + 0) >> 2, (t + 256) >> 2 };
    const int ak4   = (t & 3) << 2;

    float acc[4][4][4];
#pragma unroll
    for (int i = 0; i < 4; i++)
#pragma unroll
        for (int j = 0; j < 4; j++)
#pragma unroll
            for (int k = 0; k < 4; k++) acc[i][j][k] = 0.f;

    auto issue = [&](int stage, int kc) {
        uint32_t* As_ = smA + stage * A_STAGE_WORDS;
        uint32_t* Bs_ = smB + stage * BSTW;
#pragma unroll
        for (int rep = 0; rep < 2; rep++) {
            int m = am[rep];
            cpa16(As_ + m * A_ROW_STRIDE + ak4,
                  X + (size_t)(m0 + m) * D_MODEL + kc * 16 + ak4);
        }
#pragma unroll
        for (int rep = 0; rep < 2; rep++) {
            int f = t + rep * 256;
            if (MODE == 0) {
                int k = f >> 5, n4 = (f & 31) << 2;
                int bn = n0 + n4;
                int ck = ((k >> 2) & 3) << 2;
                cpa16(Bs_ + k * 136 + (n4 ^ ck),
                      W + (size_t)(bn >> 6) * (D_MODEL * DK)
                        + (size_t)(kc * 16 + k) * DK + (bn & 63));
            } else {
                int n = f >> 2, k4 = (f & 3) << 2;
                cpa16(Bs_ + n * A_ROW_STRIDE + k4,
                      W + (size_t)(n0 + n) * D_MODEL + kc * 16 + k4);
            }
        }
    };

    auto compute = [&](int stage) {
        uint32_t* As_ = smA + stage * A_STAGE_WORDS;
        uint32_t* Bs_ = smB + stage * BSTW;
#pragma unroll
        for (int ks = 0; ks < 2; ks++) {
            const int kb = ks * 8;
            uint32_t af[4][4];
#pragma unroll
            for (int mt = 0; mt < 4; mt++) {
                const int r = (wm + mt * 16 + gid) * A_ROW_STRIDE;
                af[mt][0] = As_[r + kb + tig];
                af[mt][1] = As_[r + 8 * A_ROW_STRIDE + kb + tig];
                af[mt][2] = As_[r + kb + tig + 4];
                af[mt][3] = As_[r + 8 * A_ROW_STRIDE + kb + tig + 4];
            }
            uint32_t bf[4][2];
#pragma unroll
            for (int nt = 0; nt < 4; nt++) {
                const int ncol = wn + nt * 8 + gid;
                if (MODE == 0) {
                    const int x0 = ks ? 8 : 0;
                    const int x1 = ks ? 12 : 4;
                    bf[nt][0] = Bs_[(kb + tig) * 136 + (ncol ^ x0)];
                    bf[nt][1] = Bs_[(kb + tig + 4) * 136 + (ncol ^ x1)];
                } else {
                    bf[nt][0] = Bs_[ncol * A_ROW_STRIDE + kb + tig];
                    bf[nt][1] = Bs_[ncol * A_ROW_STRIDE + kb + tig + 4];
                }
            }
#pragma unroll
            for (int mt = 0; mt < 4; mt++)
#pragma unroll
                for (int nt = 0; nt < 4; nt++) mma_tf32(acc[mt][nt], af[mt], bf[nt]);
        }
    };

    issue(0, 0); cpa_commit();
    issue(1, 1); cpa_commit();
    issue(2, 2); cpa_commit();
    for (int kc = 0; kc < 64; kc++) {
        cpa_wait<2>();
        __syncthreads();
        compute(kc & 3);
        if (kc + 3 < 64) issue((kc + 3) & 3, kc + 3);
        cpa_commit();
    }

#pragma unroll
    for (int mt = 0; mt < 4; mt++) {
#pragma unroll
        for (int nt = 0; nt < 4; nt++) {
            const int r0 = m0 + wm + mt * 16 + gid;
            const int r1 = r0 + 8;
            const int c  = n0 + wn + nt * 8 + tig * 2;
            const float bv0 = bias[c], bv1 = bias[c + 1];
            float2 v0 = make_float2(acc[mt][nt][0] + bv0, acc[mt][nt][1] + bv1);
            float2 v1 = make_float2(acc[mt][nt][2] + bv0, acc[mt][nt][3] + bv1);
            if (MODE == 0) {
                const int h = c >> 6, kd = c & 63;
                const int b0_ = r0 >> 11, s0 = r0 & 2047;
                const int b1_ = r1 >> 11, s1 = r1 & 2047;
                *(float2*)(out + (((size_t)b0_ * NUM_HEADS + h) * SEQ + s0) * DK + kd) = v0;
                *(float2*)(out + (((size_t)b1_ * NUM_HEADS + h) * SEQ + s1) * DK + kd) = v1;
            } else {
                *(float2*)(out + (size_t)r0 * D_MODEL + c) = v0;
                *(float2*)(out + (size_t)r1 * D_MODEL + c) = v1;
            }
        }
    }
}

// proj wrapper (R9 exact): grid.z selects Q/K/V
struct ProjArgs {
    const float* X[3];
    const float* W[3];
    const float* bias[3];
    float* out[3];
};

__global__ __launch_bounds__(256, 2) void proj_gemm3_v3_kernel(ProjArgs args)
{
    extern __shared__ uint32_t sg[];
    const int z = blockIdx.z;
    const float* X    = args.X[z];
    const float* W    = args.W[z];
    const float* bias = args.bias[z];
    float* out        = args.out[z];

    uint32_t* smA = sg;
    uint32_t* smB = sg + NSTAGE * A_STAGE_WORDS;

    const int t    = threadIdx.x;
    const int n0   = blockIdx.x * 128;
    const int m0   = blockIdx.y * 128;
    const int warp = t >> 5;
    const int lane = t & 31;
    const int gid  = lane >> 2;
    const int tig  = lane & 3;
    const int wm   = (warp & 1) * 64;
    const int wn   = (warp >> 1) * 32;

    const int am[2] = { (t + 0) >> 2, (t + 256) >> 2 };
    const int ak4   = (t & 3) << 2;

    float acc[4][4][4];
#pragma unroll
    for (int i = 0; i < 4; i++)
#pragma unroll
        for (int j = 0; j < 4; j++)
#pragma unroll
            for (int k = 0; k < 4; k++) acc[i][j][k] = 0.f;

    auto issue = [&](int stage, int kc) {
        uint32_t* As_ = smA + stage * A_STAGE_WORDS;
        uint32_t* Bs_ = smB + stage * B0_STAGE_WORDS;
#pragma unroll
        for (int rep = 0; rep < 2; rep++) {
            int m = am[rep];
            cpa16(As_ + m * A_ROW_STRIDE + ak4,
                  X + (size_t)(m0 + m) * D_MODEL + kc * 16 + ak4);
        }
#pragma unroll
        for (int rep = 0; rep < 2; rep++) {
            int f = t + rep * 256;
            int k = f >> 5, n4 = (f & 31) << 2;
            int bn = n0 + n4;
            int ck = ((k >> 2) & 3) << 2;
            cpa16(Bs_ + k * 136 + (n4 ^ ck),
                  W + (size_t)(bn >> 6) * (D_MODEL * DK)
                    + (size_t)(kc * 16 + k) * DK + (bn & 63));
        }
    };

    auto compute = [&](int stage) {
        uint32_t* As_ = smA + stage * A_STAGE_WORDS;
        uint32_t* Bs_ = smB + stage * B0_STAGE_WORDS;
#pragma unroll
        for (int ks = 0; ks < 2; ks++) {
            const int kb = ks * 8;
            const int x0 = ks ? 8 : 0;
            const int x1 = ks ? 12 : 4;
            uint32_t af[4][4];
#pragma unroll
            for (int mt = 0; mt < 4; mt++) {
                const int r = (wm + mt * 16 + gid) * A_ROW_STRIDE;
                af[mt][0] = As_[r + kb + tig];
                af[mt][1] = As_[r + 8 * A_ROW_STRIDE + kb + tig];
                af[mt][2] = As_[r + kb + tig + 4];
                af[mt][3] = As_[r + 8 * A_ROW_STRIDE + kb + tig + 4];
            }
            uint32_t bf[4][2];
#pragma unroll
            for (int nt = 0; nt < 4; nt++) {
                const int ncol = wn + nt * 8 + gid;
                bf[nt][0] = Bs_[(kb + tig) * 136 + (ncol ^ x0)];
                bf[nt][1] = Bs_[(kb + tig + 4) * 136 + (ncol ^ x1)];
            }
#pragma unroll
            for (int mt = 0; mt < 4; mt++)
#pragma unroll
                for (int nt = 0; nt < 4; nt++) mma_tf32(acc[mt][nt], af[mt], bf[nt]);
        }
    };

    issue(0, 0); cpa_commit();
    issue(1, 1); cpa_commit();
    issue(2, 2); cpa_commit();
    for (int kc = 0; kc < 64; kc++) {
        cpa_wait<2>();
        __syncthreads();
        compute(kc & 3);
        if (kc + 3 < 64) issue((kc + 3) & 3, kc + 3);
        cpa_commit();
    }

#pragma unroll
    for (int mt = 0; mt < 4; mt++) {
#pragma unroll
        for (int nt = 0; nt < 4; nt++) {
            const int r0 = m0 + wm + mt * 16 + gid;
            const int r1 = r0 + 8;
            const int c  = n0 + wn + nt * 8 + tig * 2;
            const float bv0 = bias[c], bv1 = bias[c + 1];
            float2 v0 = make_float2(acc[mt][nt][0] + bv0, acc[mt][nt][1] + bv1);
            float2 v1 = make_float2(acc[mt][nt][2] + bv0, acc[mt][nt][3] + bv1);
            const int h = c >> 6, kd = c & 63;
            const int b0_ = r0 >> 11, s0 = r0 & 2047;
            const int b1_ = r1 >> 11, s1 = r1 & 2047;
            *(float2*)(out + (((size_t)b0_ * NUM_HEADS + h) * SEQ + s0) * DK + kd) = v0;
            *(float2*)(out + (((size_t)b1_ * NUM_HEADS + h) * SEQ + s1) * DK + kd) = v1;
        }
    }
}

// =====================================================================
// Flash attention (R9 skeleton + softmax-chain reorder):
//  - o-rescale moved BEFORE the exp loop (fills MUFU shadow)
//  - p shfl-reduction + l-update deferred until AFTER the PV mmas
// Arithmetic and rounding points identical to R9.
// =====================================================================
__global__ __launch_bounds__(256, 2) void flash_mma_kernel()
{
    extern __shared__ uint32_t smu[];
    uint32_t* KsB = smu;                  // 2 x [64][KRS] (rows permuted)
    uint32_t* VsB = smu + 2 * KB_WORDS;   // 2 x [64][VRS] (rows natural)

    const int t    = threadIdx.x;
    const int warp = t >> 5;
    const int lane = t & 31;
    const int gid  = lane >> 2;
    const int tig  = lane & 3;
    const int q0   = blockIdx.x * 128;
    const int bh   = blockIdx.y;

    const float* qb = g_q + (size_t)bh * SEQ * DK;
    const float* kb = g_k + (size_t)bh * SEQ * DK;
    const float* vb = g_v + (size_t)bh * SEQ * DK;

    const int r0 = q0 + warp * 16 + gid;
    const int r1 = r0 + 8;
    uint32_t qf[8][4];
#pragma unroll
    for (int kk = 0; kk < 8; kk++) {
        qf[kk][0] = f2tf(qb[(size_t)r0 * DK + kk * 8 + tig]     * 0.125f);
        qf[kk][1] = f2tf(qb[(size_t)r1 * DK + kk * 8 + tig]     * 0.125f);
        qf[kk][2] = f2tf(qb[(size_t)r0 * DK + kk * 8 + tig + 4] * 0.125f);
        qf[kk][3] = f2tf(qb[(size_t)r1 * DK + kk * 8 + tig + 4] * 0.125f);
    }

    float m0 = -INFINITY, m1 = -INFINITY, l0 = 0.f, l1 = 0.f;
    float o[8][4];
#pragma unroll
    for (int j = 0; j < 8; j++)
#pragma unroll
        for (int k = 0; k < 4; k++) o[j][k] = 0.f;

    const int crow[4] = { (t + 0) >> 4, (t + 256) >> 4, (t + 512) >> 4, (t + 768) >> 4 };
    const int cc4     = (t & 15) << 2;

    auto issue_kv = [&](int buf, int s0) {
        uint32_t* Ks_ = KsB + buf * KB_WORDS;
        uint32_t* Vs_ = VsB + buf * VB_WORDS;
#pragma unroll
        for (int rep = 0; rep < 4; rep++) {
            int row  = crow[rep];
            int prow = (row & ~7) | ((row & 3) << 1) | ((row >> 2) & 1);
            cpa16(Ks_ + prow * KRS + cc4, kb + (size_t)(s0 + row) * DK + cc4);
            cpa16(Vs_ + row  * VRS + cc4, vb + (size_t)(s0 + row) * DK + cc4);
        }
        cpa_commit();
    };

    issue_kv(0, 0);

    for (int tile = 0; tile < SEQ / 64; tile++) {
        const int buf = tile & 1;
        uint32_t* Ks = KsB + buf * KB_WORDS;
        uint32_t* Vs = VsB + buf * VB_WORDS;

        cpa_wait<0>();
        __syncthreads();
        if (tile + 1 < SEQ / 64) issue_kv(buf ^ 1, (tile + 1) * 64);

        // ---- S = Q K^T (K rows permuted -> C-frag in A-frag order) ----
        float sacc[8][4];
#pragma unroll
        for (int j = 0; j < 8; j++)
#pragma unroll
            for (int k = 0; k < 4; k++) sacc[j][k] = 0.f;
#pragma unroll
        for (int kk = 0; kk < 8; kk++) {
            uint32_t bf[8][2];
#pragma unroll
            for (int j = 0; j < 8; j++) {
                bf[j][0] = Ks[(j * 8 + gid) * KRS + kk * 8 + tig];
                bf[j][1] = Ks[(j * 8 + gid) * KRS + kk * 8 + tig + 4];
            }
#pragma unroll
            for (int j = 0; j < 8; j++) mma_tf32(sacc[j], qf[kk], bf[j]);
        }

        // ---- fragment-resident online softmax ----
        float t0 = -INFINITY, t1 = -INFINITY;
#pragma unroll
        for (int j = 0; j < 8; j++) {
            t0 = fmaxf(t0, fmaxf(sacc[j][0], sacc[j][1]));
            t1 = fmaxf(t1, fmaxf(sacc[j][2], sacc[j][3]));
        }
        t0 = fmaxf(t0, __shfl_xor_sync(0xffffffffu, t0, 1));
        t0 = fmaxf(t0, __shfl_xor_sync(0xffffffffu, t0, 2));
        t1 = fmaxf(t1, __shfl_xor_sync(0xffffffffu, t1, 1));
        t1 = fmaxf(t1, __shfl_xor_sync(0xffffffffu, t1, 2));

        float nm0 = fmaxf(m0, t0), nm1 = fmaxf(m1, t1);
        float a0 = __expf(m0 - nm0), a1 = __expf(m1 - nm1);
        m0 = nm0; m1 = nm1;

        // o-rescale FIRST (independent of exps; overlaps MUFU work below)
#pragma unroll
        for (int j = 0; j < 8; j++) {
            o[j][0] *= a0; o[j][1] *= a0;
            o[j][2] *= a1; o[j][3] *= a1;
        }

        float p0 = 0.f, p1 = 0.f;
#pragma unroll
        for (int j = 0; j < 8; j++) {
            float e0 = __expf(sacc[j][0] - nm0);
            float e1 = __expf(sacc[j][1] - nm0);
            float e2 = __expf(sacc[j][2] - nm1);
            float e3 = __expf(sacc[j][3] - nm1);
            p0 += e0 + e1;
            p1 += e2 + e3;
            sacc[j][0] = __uint_as_float(f2tf(e0));
            sacc[j][1] = __uint_as_float(f2tf(e1));
            sacc[j][2] = __uint_as_float(f2tf(e2));
            sacc[j][3] = __uint_as_float(f2tf(e3));
        }

        // ---- O += P V (P in registers, A-frag order {e0,e2,e1,e3}) ----
#pragma unroll
        for (int kk = 0; kk < 8; kk++) {
            uint32_t af[4];
            af[0] = __float_as_uint(sacc[kk][0]);
            af[1] = __float_as_uint(sacc[kk][2]);
            af[2] = __float_as_uint(sacc[kk][1]);
            af[3] = __float_as_uint(sacc[kk][3]);
#pragma unroll
            for (int j = 0; j < 8; j++) {
                uint32_t bf[2];
                bf[0] = Vs[(kk * 8 + tig) * VRS + j * 8 + gid];
                bf[1] = Vs[(kk * 8 + tig + 4) * VRS + j * 8 + gid];
                mma_tf32(o[j], af, bf);
            }
        }

        // deferred p reduction + l update (hidden under PV above)
        p0 += __shfl_xor_sync(0xffffffffu, p0, 1);
        p0 += __shfl_xor_sync(0xffffffffu, p0, 2);
        p1 += __shfl_xor_sync(0xffffffffu, p1, 1);
        p1 += __shfl_xor_sync(0xffffffffu, p1, 2);
        l0 = l0 * a0 + p0;
        l1 = l1 * a1 + p1;
    }

    const float i0 = 1.f / l0, i1 = 1.f / l1;
    const int b_ = bh >> 4, h = bh & 15;
    float* row0 = g_cat + (size_t)(b_ * SEQ + r0) * D_MODEL + h * DK;
    float* row1 = g_cat + (size_t)(b_ * SEQ + r1) * D_MODEL + h * DK;
#pragma unroll
    for (int j = 0; j < 8; j++) {
        *(float2*)(row0 + j * 8 + tig * 2) = make_float2(o[j][0] * i0, o[j][1] * i0);
        *(float2*)(row1 + j * 8 + tig * 2) = make_float2(o[j][2] * i1, o[j][3] * i1);
    }
}

extern "C" void kernel_launch(void* const* d_in, const int* in_sizes, int n_in,
                              void* d_out, int out_size)
{
    const float* Q  = (const float*)d_in[0];
    const float* K  = (const float*)d_in[1];
    const float* V  = (const float*)d_in[2];
    const float* Wq = (const float*)d_in[3];
    const float* bq = (const float*)d_in[4];
    const float* Wk = (const float*)d_in[5];
    const float* bk = (const float*)d_in[6];
    const float* Wv = (const float*)d_in[7];
    const float* bv = (const float*)d_in[8];
    const float* Wo = (const float*)d_in[9];
    const float* bo = (const float*)d_in[10];
    float* out = (float*)d_out;

    float *gq, *gk, *gv, *gcat;
    cudaGetSymbolAddress((void**)&gq, g_q);
    cudaGetSymbolAddress((void**)&gk, g_k);
    cudaGetSymbolAddress((void**)&gv, g_v);
    cudaGetSymbolAddress((void**)&gcat, g_cat);

    const int proj_smem  = (NSTAGE * A_STAGE_WORDS + NSTAGE * B0_STAGE_WORDS) * 4; // 75776
    const int outg_smem  = (NSTAGE * A_STAGE_WORDS + NSTAGE * B1_STAGE_WORDS) * 4; // 81920
    const int flash_smem = (2 * KB_WORDS + 2 * VB_WORDS) * 4;                      // 71680

    cudaFuncSetAttribute(proj_gemm3_v3_kernel,
                         cudaFuncAttributeMaxDynamicSharedMemorySize, proj_smem);
    cudaFuncSetAttribute(gemm_v3_kernel<1>,
                         cudaFuncAttributeMaxDynamicSharedMemorySize, outg_smem);
    cudaFuncSetAttribute(flash_mma_kernel,
                         cudaFuncAttributeMaxDynamicSharedMemorySize, flash_smem);

    ProjArgs pa;
    pa.X[0] = Q;  pa.X[1] = K;  pa.X[2] = V;
    pa.W[0] = Wq; pa.W[1] = Wk; pa.W[2] = Wv;
    pa.bias[0] = bq; pa.bias[1] = bk; pa.bias[2] = bv;
    pa.out[0] = gq; pa.out[1] = gk; pa.out[2] = gv;

    dim3 pgrd(D_MODEL / 128, M_TOTAL / 128, 3);
    proj_gemm3_v3_kernel<<<pgrd, dim3(256), proj_smem>>>(pa);

    dim3 fgrd(SEQ / 128, BATCH * NUM_HEADS);
    flash_mma_kernel<<<fgrd, dim3(256), flash_smem>>>();

    dim3 ogrd(D_MODEL / 128, M_TOTAL / 128);
    gemm_v3_kernel<1><<<ogrd, dim3(256), outg_smem>>>(gcat, Wo, bo, out);
}

// round 16
// speedup vs baseline: 1.0442x; 1.0163x over previous
#include <cuda_runtime.h>
#include <math.h>
#include <stdint.h>

#define D_MODEL 1024
#define NUM_HEADS 16
#define DK 64
#define BATCH 2
#define SEQ 2048
#define M_TOTAL (BATCH * SEQ)  // 4096

// GEMM smem geometry (4-stage cp.async)
#define A_ROW_STRIDE 20
#define A_STAGE_WORDS (128 * A_ROW_STRIDE)
#define B0_STAGE_WORDS (16 * 136)
#define B1_STAGE_WORDS (128 * A_ROW_STRIDE)
#define NSTAGE 4

// flash smem strides (R9, known-good): K/P loads gid*stride+tig -> stride%32==4;
// V loads tig*stride+gid -> stride%32==8. K/V TRIPLE-buffered (cp.async).
#define KRS 68
#define VRS 72
#define KB_WORDS (64 * KRS)     // 4352 per buffer
#define VB_WORDS (64 * VRS)     // 4608 per buffer
#define NBUF 3

__device__ float g_q[BATCH * NUM_HEADS * SEQ * DK];
__device__ float g_k[BATCH * NUM_HEADS * SEQ * DK];
__device__ float g_v[BATCH * NUM_HEADS * SEQ * DK];
__device__ float g_cat[M_TOTAL * D_MODEL];

__device__ __forceinline__ uint32_t f2tf(float f) {
    uint32_t u;
    asm("cvt.rna.tf32.f32 %0, %1;" : "=r"(u) : "f"(f));
    return u;
}

__device__ __forceinline__ void mma_tf32(float* c, const uint32_t* a, const uint32_t* b) {
    asm volatile(
        "mma.sync.aligned.m16n8k8.row.col.f32.tf32.tf32.f32 "
        "{%0,%1,%2,%3}, {%4,%5,%6,%7}, {%8,%9}, {%0,%1,%2,%3};"
        : "+f"(c[0]), "+f"(c[1]), "+f"(c[2]), "+f"(c[3])
        : "r"(a[0]), "r"(a[1]), "r"(a[2]), "r"(a[3]), "r"(b[0]), "r"(b[1]));
}

__device__ __forceinline__ void cpa16(uint32_t* smem_dst, const float* gsrc) {
    uint32_t s = (uint32_t)__cvta_generic_to_shared(smem_dst);
    asm volatile("cp.async.cg.shared.global [%0], [%1], 16;" :: "r"(s), "l"(gsrc));
}
__device__ __forceinline__ void cpa_commit() {
    asm volatile("cp.async.commit_group;");
}
template <int N>
__device__ __forceinline__ void cpa_wait() {
    asm volatile("cp.async.wait_group %0;" :: "n"(N));
}

// =====================================================================
// TF32 GEMM (R7-R9, known-good): cp.async 4-stage, ONE sync per k-chunk.
// MODE 0 (proj): out[b,h,s,kd] = X @ W[h] + bias
// MODE 1 (out):  out[m,n] = X @ Wo[n,:]^T + bo
// =====================================================================
template <int MODE>
__global__ __launch_bounds__(256, 2) void gemm_v3_kernel(
    const float* __restrict__ X, const float* __restrict__ W,
    const float* __restrict__ bias, float* __restrict__ out)
{
    extern __shared__ uint32_t sg[];
    uint32_t* smA = sg;
    uint32_t* smB = sg + NSTAGE * A_STAGE_WORDS;
    const int BSTW = (MODE == 0) ? B0_STAGE_WORDS : B1_STAGE_WORDS;

    const int t    = threadIdx.x;
    const int n0   = blockIdx.x * 128;
    const int m0   = blockIdx.y * 128;
    const int warp = t >> 5;
    const int lane = t & 31;
    const int gid  = lane >> 2;
    const int tig  = lane & 3;
    const int wm   = (warp & 1) * 64;
    const int wn   = (warp >> 1) * 32;

    const int am[2] = { (t + 0) >> 2, (t + 256) >> 2 };
    const int ak4   = (t & 3) << 2;

    float acc[4][4][4];
#pragma unroll
    for (int i = 0; i < 4; i++)
#pragma unroll
        for (int j = 0; j < 4; j++)
#pragma unroll
            for (int k = 0; k < 4; k++) acc[i][j][k] = 0.f;

    auto issue = [&](int stage, int kc) {
        uint32_t* As_ = smA + stage * A_STAGE_WORDS;
        uint32_t* Bs_ = smB + stage * BSTW;
#pragma unroll
        for (int rep = 0; rep < 2; rep++) {
            int m = am[rep];
            cpa16(As_ + m * A_ROW_STRIDE + ak4,
                  X + (size_t)(m0 + m) * D_MODEL + kc * 16 + ak4);
        }
#pragma unroll
        for (int rep = 0; rep < 2; rep++) {
            int f = t + rep * 256;
            if (MODE == 0) {
                int k = f >> 5, n4 = (f & 31) << 2;
                int bn = n0 + n4;
                int ck = ((k >> 2) & 3) << 2;
                cpa16(Bs_ + k * 136 + (n4 ^ ck),
                      W + (size_t)(bn >> 6) * (D_MODEL * DK)
                        + (size_t)(kc * 16 + k) * DK + (bn & 63));
            } else {
                int n = f >> 2, k4 = (f & 3) << 2;
                cpa16(Bs_ + n * A_ROW_STRIDE + k4,
                      W + (size_t)(n0 + n) * D_MODEL + kc * 16 + k4);
            }
        }
    };

    auto compute = [&](int stage) {
        uint32_t* As_ = smA + stage * A_STAGE_WORDS;
        uint32_t* Bs_ = smB + stage * BSTW;
#pragma unroll
        for (int ks = 0; ks < 2; ks++) {
            const int kb = ks * 8;
            uint32_t af[4][4];
#pragma unroll
            for (int mt = 0; mt < 4; mt++) {
                const int r = (wm + mt * 16 + gid) * A_ROW_STRIDE;
                af[mt][0] = As_[r + kb + tig];
                af[mt][1] = As_[r + 8 * A_ROW_STRIDE + kb + tig];
                af[mt][2] = As_[r + kb + tig + 4];
                af[mt][3] = As_[r + 8 * A_ROW_STRIDE + kb + tig + 4];
            }
            uint32_t bf[4][2];
#pragma unroll
            for (int nt = 0; nt < 4; nt++) {
                const int ncol = wn + nt * 8 + gid;
                if (MODE == 0) {
                    const int x0 = ks ? 8 : 0;
                    const int x1 = ks ? 12 : 4;
                    bf[nt][0] = Bs_[(kb + tig) * 136 + (ncol ^ x0)];
                    bf[nt][1] = Bs_[(kb + tig + 4) * 136 + (ncol ^ x1)];
                } else {
                    bf[nt][0] = Bs_[ncol * A_ROW_STRIDE + kb + tig];
                    bf[nt][1] = Bs_[ncol * A_ROW_STRIDE + kb + tig + 4];
                }
            }
#pragma unroll
            for (int mt = 0; mt < 4; mt++)
#pragma unroll
                for (int nt = 0; nt < 4; nt++) mma_tf32(acc[mt][nt], af[mt], bf[nt]);
        }
    };

    issue(0, 0); cpa_commit();
    issue(1, 1); cpa_commit();
    issue(2, 2); cpa_commit();
    for (int kc = 0; kc < 64; kc++) {
        cpa_wait<2>();
        __syncthreads();
        compute(kc & 3);
        if (kc + 3 < 64) issue((kc + 3) & 3, kc + 3);
        cpa_commit();
    }

#pragma unroll
    for (int mt = 0; mt < 4; mt++) {
#pragma unroll
        for (int nt = 0; nt < 4; nt++) {
            const int r0 = m0 + wm + mt * 16 + gid;
            const int r1 = r0 + 8;
            const int c  = n0 + wn + nt * 8 + tig * 2;
            const float bv0 = bias[c], bv1 = bias[c + 1];
            float2 v0 = make_float2(acc[mt][nt][0] + bv0, acc[mt][nt][1] + bv1);
            float2 v1 = make_float2(acc[mt][nt][2] + bv0, acc[mt][nt][3] + bv1);
            if (MODE == 0) {
                const int h = c >> 6, kd = c & 63;
                const int b0_ = r0 >> 11, s0 = r0 & 2047;
                const int b1_ = r1 >> 11, s1 = r1 & 2047;
                *(float2*)(out + (((size_t)b0_ * NUM_HEADS + h) * SEQ + s0) * DK + kd) = v0;
                *(float2*)(out + (((size_t)b1_ * NUM_HEADS + h) * SEQ + s1) * DK + kd) = v1;
            } else {
                *(float2*)(out + (size_t)r0 * D_MODEL + c) = v0;
                *(float2*)(out + (size_t)r1 * D_MODEL + c) = v1;
            }
        }
    }
}

// proj wrapper (R9 exact): grid.z selects Q/K/V
struct ProjArgs {
    const float* X[3];
    const float* W[3];
    const float* bias[3];
    float* out[3];
};

__global__ __launch_bounds__(256, 2) void proj_gemm3_v3_kernel(ProjArgs args)
{
    extern __shared__ uint32_t sg[];
    const int z = blockIdx.z;
    const float* X    = args.X[z];
    const float* W    = args.W[z];
    const float* bias = args.bias[z];
    float* out        = args.out[z];

    uint32_t* smA = sg;
    uint32_t* smB = sg + NSTAGE * A_STAGE_WORDS;

    const int t    = threadIdx.x;
    const int n0   = blockIdx.x * 128;
    const int m0   = blockIdx.y * 128;
    const int warp = t >> 5;
    const int lane = t & 31;
    const int gid  = lane >> 2;
    const int tig  = lane & 3;
    const int wm   = (warp & 1) * 64;
    const int wn   = (warp >> 1) * 32;

    const int am[2] = { (t + 0) >> 2, (t + 256) >> 2 };
    const int ak4   = (t & 3) << 2;

    float acc[4][4][4];
#pragma unroll
    for (int i = 0; i < 4; i++)
#pragma unroll
        for (int j = 0; j < 4; j++)
#pragma unroll
            for (int k = 0; k < 4; k++) acc[i][j][k] = 0.f;

    auto issue = [&](int stage, int kc) {
        uint32_t* As_ = smA + stage * A_STAGE_WORDS;
        uint32_t* Bs_ = smB + stage * B0_STAGE_WORDS;
#pragma unroll
        for (int rep = 0; rep < 2; rep++) {
            int m = am[rep];
            cpa16(As_ + m * A_ROW_STRIDE + ak4,
                  X + (size_t)(m0 + m) * D_MODEL + kc * 16 + ak4);
        }
#pragma unroll
        for (int rep = 0; rep < 2; rep++) {
            int f = t + rep * 256;
            int k = f >> 5, n4 = (f & 31) << 2;
            int bn = n0 + n4;
            int ck = ((k >> 2) & 3) << 2;
            cpa16(Bs_ + k * 136 + (n4 ^ ck),
                  W + (size_t)(bn >> 6) * (D_MODEL * DK)
                    + (size_t)(kc * 16 + k) * DK + (bn & 63));
        }
    };

    auto compute = [&](int stage) {
        uint32_t* As_ = smA + stage * A_STAGE_WORDS;
        uint32_t* Bs_ = smB + stage * B0_STAGE_WORDS;
#pragma unroll
        for (int ks = 0; ks < 2; ks++) {
            const int kb = ks * 8;
            const int x0 = ks ? 8 : 0;
            const int x1 = ks ? 12 : 4;
            uint32_t af[4][4];
#pragma unroll
            for (int mt = 0; mt < 4; mt++) {
                const int r = (wm + mt * 16 + gid) * A_ROW_STRIDE;
                af[mt][0] = As_[r + kb + tig];
                af[mt][1] = As_[r + 8 * A_ROW_STRIDE + kb + tig];
                af[mt][2] = As_[r + kb + tig + 4];
                af[mt][3] = As_[r + 8 * A_ROW_STRIDE + kb + tig + 4];
            }
            uint32_t bf[4][2];
#pragma unroll
            for (int nt = 0; nt < 4; nt++) {
                const int ncol = wn + nt * 8 + gid;
                bf[nt][0] = Bs_[(kb + tig) * 136 + (ncol ^ x0)];
                bf[nt][1] = Bs_[(kb + tig + 4) * 136 + (ncol ^ x1)];
            }
#pragma unroll
            for (int mt = 0; mt < 4; mt++)
#pragma unroll
                for (int nt = 0; nt < 4; nt++) mma_tf32(acc[mt][nt], af[mt], bf[nt]);
        }
    };

    issue(0, 0); cpa_commit();
    issue(1, 1); cpa_commit();
    issue(2, 2); cpa_commit();
    for (int kc = 0; kc < 64; kc++) {
        cpa_wait<2>();
        __syncthreads();
        compute(kc & 3);
        if (kc + 3 < 64) issue((kc + 3) & 3, kc + 3);
        cpa_commit();
    }

#pragma unroll
    for (int mt = 0; mt < 4; mt++) {
#pragma unroll
        for (int nt = 0; nt < 4; nt++) {
            const int r0 = m0 + wm + mt * 16 + gid;
            const int r1 = r0 + 8;
            const int c  = n0 + wn + nt * 8 + tig * 2;
            const float bv0 = bias[c], bv1 = bias[c + 1];
            float2 v0 = make_float2(acc[mt][nt][0] + bv0, acc[mt][nt][1] + bv1);
            float2 v1 = make_float2(acc[mt][nt][2] + bv0, acc[mt][nt][3] + bv1);
            const int h = c >> 6, kd = c & 63;
            const int b0_ = r0 >> 11, s0 = r0 & 2047;
            const int b1_ = r1 >> 11, s1 = r1 & 2047;
            *(float2*)(out + (((size_t)b0_ * NUM_HEADS + h) * SEQ + s0) * DK + kd) = v0;
            *(float2*)(out + (((size_t)b1_ * NUM_HEADS + h) * SEQ + s1) * DK + kd) = v1;
        }
    }
}

// =====================================================================
// Flash attention (R9 skeleton + exp2 folding + triple-buffered K/V):
//  - Q fragments pre-scaled by 0.125*log2(e); exps become bare exp2f
//    (MUFU.EX2, no FMUL) -- same values within 1 ulp.
//  - 3 K/V buffers, copy issued 2 tiles ahead, wait<1> per tile;
//    one commit per iteration unconditionally (tail-safe).
// =====================================================================
__global__ __launch_bounds__(256, 2) void flash_mma_kernel()
{
    extern __shared__ uint32_t smu[];
    uint32_t* KsB = smu;                     // NBUF x [64][KRS] (rows permuted)
    uint32_t* VsB = smu + NBUF * KB_WORDS;   // NBUF x [64][VRS] (rows natural)

    const int t    = threadIdx.x;
    const int warp = t >> 5;
    const int lane = t & 31;
    const int gid  = lane >> 2;
    const int tig  = lane & 3;
    const int q0   = blockIdx.x * 128;
    const int bh   = blockIdx.y;

    const float* qb = g_q + (size_t)bh * SEQ * DK;
    const float* kb = g_k + (size_t)bh * SEQ * DK;
    const float* vb = g_v + (size_t)bh * SEQ * DK;

    const int r0 = q0 + warp * 16 + gid;
    const int r1 = r0 + 8;
    // scale = (1/8) * log2(e): scores computed directly in log2 domain
    const float QSCALE = 0.125f * 1.4426950408889634f;
    uint32_t qf[8][4];
#pragma unroll
    for (int kk = 0; kk < 8; kk++) {
        qf[kk][0] = f2tf(qb[(size_t)r0 * DK + kk * 8 + tig]     * QSCALE);
        qf[kk][1] = f2tf(qb[(size_t)r1 * DK + kk * 8 + tig]     * QSCALE);
        qf[kk][2] = f2tf(qb[(size_t)r0 * DK + kk * 8 + tig + 4] * QSCALE);
        qf[kk][3] = f2tf(qb[(size_t)r1 * DK + kk * 8 + tig + 4] * QSCALE);
    }

    float m0 = -INFINITY, m1 = -INFINITY, l0 = 0.f, l1 = 0.f;
    float o[8][4];
#pragma unroll
    for (int j = 0; j < 8; j++)
#pragma unroll
        for (int k = 0; k < 4; k++) o[j][k] = 0.f;

    const int crow[4] = { (t + 0) >> 4, (t + 256) >> 4, (t + 512) >> 4, (t + 768) >> 4 };
    const int cc4     = (t & 15) << 2;

    auto issue_kv = [&](int buf, int s0) {
        uint32_t* Ks_ = KsB + buf * KB_WORDS;
        uint32_t* Vs_ = VsB + buf * VB_WORDS;
#pragma unroll
        for (int rep = 0; rep < 4; rep++) {
            int row  = crow[rep];
            int prow = (row & ~7) | ((row & 3) << 1) | ((row >> 2) & 1);
            cpa16(Ks_ + prow * KRS + cc4, kb + (size_t)(s0 + row) * DK + cc4);
            cpa16(Vs_ + row  * VRS + cc4, vb + (size_t)(s0 + row) * DK + cc4);
        }
        cpa_commit();
    };

    const int NT = SEQ / 64;  // 32
    issue_kv(0, 0);
    issue_kv(1, 64);

    for (int tile = 0; tile < NT; tile++) {
        const int buf = tile % NBUF;
        uint32_t* Ks = KsB + buf * KB_WORDS;
        uint32_t* Vs = VsB + buf * VB_WORDS;

        cpa_wait<1>();   // this tile's group landed; next may be in flight
        __syncthreads();
        if (tile + 2 < NT) issue_kv((tile + 2) % NBUF, (tile + 2) * 64);
        else cpa_commit();   // empty group keeps drain order (tail-safe)

        // ---- S' = (Q*log2e/8) K^T (K rows permuted -> A-frag order) ----
        float sacc[8][4];
#pragma unroll
        for (int j = 0; j < 8; j++)
#pragma unroll
            for (int k = 0; k < 4; k++) sacc[j][k] = 0.f;
#pragma unroll
        for (int kk = 0; kk < 8; kk++) {
            uint32_t bf[8][2];
#pragma unroll
            for (int j = 0; j < 8; j++) {
                bf[j][0] = Ks[(j * 8 + gid) * KRS + kk * 8 + tig];
                bf[j][1] = Ks[(j * 8 + gid) * KRS + kk * 8 + tig + 4];
            }
#pragma unroll
            for (int j = 0; j < 8; j++) mma_tf32(sacc[j], qf[kk], bf[j]);
        }

        // ---- fragment-resident online softmax (log2 domain) ----
        float t0 = -INFINITY, t1 = -INFINITY;
#pragma unroll
        for (int j = 0; j < 8; j++) {
            t0 = fmaxf(t0, fmaxf(sacc[j][0], sacc[j][1]));
            t1 = fmaxf(t1, fmaxf(sacc[j][2], sacc[j][3]));
        }
        t0 = fmaxf(t0, __shfl_xor_sync(0xffffffffu, t0, 1));
        t0 = fmaxf(t0, __shfl_xor_sync(0xffffffffu, t0, 2));
        t1 = fmaxf(t1, __shfl_xor_sync(0xffffffffu, t1, 1));
        t1 = fmaxf(t1, __shfl_xor_sync(0xffffffffu, t1, 2));

        float nm0 = fmaxf(m0, t0), nm1 = fmaxf(m1, t1);
        float a0 = exp2f(m0 - nm0), a1 = exp2f(m1 - nm1);
        m0 = nm0; m1 = nm1;

        float p0 = 0.f, p1 = 0.f;
#pragma unroll
        for (int j = 0; j < 8; j++) {
            float e0 = exp2f(sacc[j][0] - nm0);
            float e1 = exp2f(sacc[j][1] - nm0);
            float e2 = exp2f(sacc[j][2] - nm1);
            float e3 = exp2f(sacc[j][3] - nm1);
            p0 += e0 + e1;
            p1 += e2 + e3;
            sacc[j][0] = __uint_as_float(f2tf(e0));
            sacc[j][1] = __uint_as_float(f2tf(e1));
            sacc[j][2] = __uint_as_float(f2tf(e2));
            sacc[j][3] = __uint_as_float(f2tf(e3));
        }
        p0 += __shfl_xor_sync(0xffffffffu, p0, 1);
        p0 += __shfl_xor_sync(0xffffffffu, p0, 2);
        p1 += __shfl_xor_sync(0xffffffffu, p1, 1);
        p1 += __shfl_xor_sync(0xffffffffu, p1, 2);
        l0 = l0 * a0 + p0;
        l1 = l1 * a1 + p1;

#pragma unroll
        for (int j = 0; j < 8; j++) {
            o[j][0] *= a0; o[j][1] *= a0;
            o[j][2] *= a1; o[j][3] *= a1;
        }

        // ---- O += P V (P in registers, A-frag order {e0,e2,e1,e3}) ----
#pragma unroll
        for (int kk = 0; kk < 8; kk++) {
            uint32_t af[4];
            af[0] = __float_as_uint(sacc[kk][0]);
            af[1] = __float_as_uint(sacc[kk][2]);
            af[2] = __float_as_uint(sacc[kk][1]);
            af[3] = __float_as_uint(sacc[kk][3]);
#pragma unroll
            for (int j = 0; j < 8; j++) {
                uint32_t bf[2];
                bf[0] = Vs[(kk * 8 + tig) * VRS + j * 8 + gid];
                bf[1] = Vs[(kk * 8 + tig + 4) * VRS + j * 8 + gid];
                mma_tf32(o[j], af, bf);
            }
        }
    }

    const float i0 = 1.f / l0, i1 = 1.f / l1;
    const int b_ = bh >> 4, h = bh & 15;
    float* row0 = g_cat + (size_t)(b_ * SEQ + r0) * D_MODEL + h * DK;
    float* row1 = g_cat + (size_t)(b_ * SEQ + r1) * D_MODEL + h * DK;
#pragma unroll
    for (int j = 0; j < 8; j++) {
        *(float2*)(row0 + j * 8 + tig * 2) = make_float2(o[j][0] * i0, o[j][1] * i0);
        *(float2*)(row1 + j * 8 + tig * 2) = make_float2(o[j][2] * i1, o[j][3] * i1);
    }
}

extern "C" void kernel_launch(void* const* d_in, const int* in_sizes, int n_in,
                              void* d_out, int out_size)
{
    const float* Q  = (const float*)d_in[0];
    const float* K  = (const float*)d_in[1];
    const float* V  = (const float*)d_in[2];
    const float* Wq = (const float*)d_in[3];
    const float* bq = (const float*)d_in[4];
    const float* Wk = (const float*)d_in[5];
    const float* bk = (const float*)d_in[6];
    const float* Wv = (const float*)d_in[7];
    const float* bv = (const float*)d_in[8];
    const float* Wo = (const float*)d_in[9];
    const float* bo = (const float*)d_in[10];
    float* out = (float*)d_out;

    float *gq, *gk, *gv, *gcat;
    cudaGetSymbolAddress((void**)&gq, g_q);
    cudaGetSymbolAddress((void**)&gk, g_k);
    cudaGetSymbolAddress((void**)&gv, g_v);
    cudaGetSymbolAddress((void**)&gcat, g_cat);

    const int proj_smem  = (NSTAGE * A_STAGE_WORDS + NSTAGE * B0_STAGE_WORDS) * 4; // 75776
    const int outg_smem  = (NSTAGE * A_STAGE_WORDS + NSTAGE * B1_STAGE_WORDS) * 4; // 81920
    const int flash_smem = NBUF * (KB_WORDS + VB_WORDS) * 4;                       // 107520

    cudaFuncSetAttribute(proj_gemm3_v3_kernel,
                         cudaFuncAttributeMaxDynamicSharedMemorySize, proj_smem);
    cudaFuncSetAttribute(gemm_v3_kernel<1>,
                         cudaFuncAttributeMaxDynamicSharedMemorySize, outg_smem);
    cudaFuncSetAttribute(flash_mma_kernel,
                         cudaFuncAttributeMaxDynamicSharedMemorySize, flash_smem);

    ProjArgs pa;
    pa.X[0] = Q;  pa.X[1] = K;  pa.X[2] = V;
    pa.W[0] = Wq; pa.W[1] = Wk; pa.W[2] = Wv;
    pa.bias[0] = bq; pa.bias[1] = bk; pa.bias[2] = bv;
    pa.out[0] = gq; pa.out[1] = gk; pa.out[2] = gv;

    dim3 pgrd(D_MODEL / 128, M_TOTAL / 128, 3);
    proj_gemm3_v3_kernel<<<pgrd, dim3(256), proj_smem>>>(pa);

    dim3 fgrd(SEQ / 128, BATCH * NUM_HEADS);
    flash_mma_kernel<<<fgrd, dim3(256), flash_smem>>>();

    dim3 ogrd(D_MODEL / 128, M_TOTAL / 128);
    gemm_v3_kernel<1><<<ogrd, dim3(256), outg_smem>>>(gcat, Wo, bo, out);
}

// round 17
// speedup vs baseline: 1.3012x; 1.2462x over previous
#include <cuda_runtime.h>
#include <cuda_fp16.h>
#include <math.h>
#include <stdint.h>

#define D_MODEL 1024
#define NUM_HEADS 16
#define DK 64
#define BATCH 2
#define SEQ 2048
#define M_TOTAL (BATCH * SEQ)  // 4096

// GEMM smem geometry (4-stage cp.async)
#define A_ROW_STRIDE 20
#define A_STAGE_WORDS (128 * A_ROW_STRIDE)
#define B0_STAGE_WORDS (16 * 136)
#define B1_STAGE_WORDS (128 * A_ROW_STRIDE)
#define NSTAGE 4

// flash fp16 smem: rows of 72 halfs = 36 words (bank: gid*36+tig == gid*4+tig mod 32)
#define FWR 36                       // words per row
#define FB_WORDS (64 * FWR)          // 2304 words = 9216 B per buffer per matrix
#define NBUF 3

__device__ __half g_q[BATCH * NUM_HEADS * SEQ * DK];   // pre-scaled by 0.125*log2(e)
__device__ __half g_k[BATCH * NUM_HEADS * SEQ * DK];   // natural [bh][s][d]
__device__ __half g_vt[BATCH * NUM_HEADS * DK * SEQ];  // transposed [bh][d][s]
__device__ float  g_cat[M_TOTAL * D_MODEL];

__device__ __forceinline__ void mma_tf32(float* c, const uint32_t* a, const uint32_t* b) {
    asm volatile(
        "mma.sync.aligned.m16n8k8.row.col.f32.tf32.tf32.f32 "
        "{%0,%1,%2,%3}, {%4,%5,%6,%7}, {%8,%9}, {%0,%1,%2,%3};"
        : "+f"(c[0]), "+f"(c[1]), "+f"(c[2]), "+f"(c[3])
        : "r"(a[0]), "r"(a[1]), "r"(a[2]), "r"(a[3]), "r"(b[0]), "r"(b[1]));
}
__device__ __forceinline__ void mma_f16(float* c, const uint32_t* a, uint32_t b0, uint32_t b1) {
    asm volatile(
        "mma.sync.aligned.m16n8k16.row.col.f32.f16.f16.f32 "
        "{%0,%1,%2,%3}, {%4,%5,%6,%7}, {%8,%9}, {%0,%1,%2,%3};"
        : "+f"(c[0]), "+f"(c[1]), "+f"(c[2]), "+f"(c[3])
        : "r"(a[0]), "r"(a[1]), "r"(a[2]), "r"(a[3]), "r"(b0), "r"(b1));
}

__device__ __forceinline__ void cpa16(uint32_t* smem_dst, const void* gsrc) {
    uint32_t s = (uint32_t)__cvta_generic_to_shared(smem_dst);
    asm volatile("cp.async.cg.shared.global [%0], [%1], 16;" :: "r"(s), "l"(gsrc));
}
__device__ __forceinline__ void cpa_commit() {
    asm volatile("cp.async.commit_group;");
}
template <int N>
__device__ __forceinline__ void cpa_wait() {
    asm volatile("cp.async.wait_group %0;" :: "n"(N));
}
__device__ __forceinline__ uint32_t packh2(float a, float b) {
    __half2 h = __floats2half2_rn(a, b);
    return *(uint32_t*)&h;
}

// =====================================================================
// Out-projection GEMM (R7-R16 template, known-good, unchanged).
// =====================================================================
template <int MODE>
__global__ __launch_bounds__(256, 2) void gemm_v3_kernel(
    const float* __restrict__ X, const float* __restrict__ W,
    const float* __restrict__ bias, float* __restrict__ out)
{
    extern __shared__ uint32_t sg[];
    uint32_t* smA = sg;
    uint32_t* smB = sg + NSTAGE * A_STAGE_WORDS;
    const int BSTW = (MODE == 0) ? B0_STAGE_WORDS : B1_STAGE_WORDS;

    const int t    = threadIdx.x;
    const int n0   = blockIdx.x * 128;
    const int m0   = blockIdx.y * 128;
    const int warp = t >> 5;
    const int lane = t & 31;
    const int gid  = lane >> 2;
    const int tig  = lane & 3;
    const int wm   = (warp & 1) * 64;
    const int wn   = (warp >> 1) * 32;

    const int am[2] = { (t + 0) >> 2, (t + 256) >> 2 };
    const int ak4   = (t & 3) << 2;

    float acc[4][4][4];
#pragma unroll
    for (int i = 0; i < 4; i++)
#pragma unroll
        for (int j = 0; j < 4; j++)
#pragma unroll
            for (int k = 0; k < 4; k++) acc[i][j][k] = 0.f;

    auto issue = [&](int stage, int kc) {
        uint32_t* As_ = smA + stage * A_STAGE_WORDS;
        uint32_t* Bs_ = smB + stage * BSTW;
#pragma unroll
        for (int rep = 0; rep < 2; rep++) {
            int m = am[rep];
            cpa16(As_ + m * A_ROW_STRIDE + ak4,
                  X + (size_t)(m0 + m) * D_MODEL + kc * 16 + ak4);
        }
#pragma unroll
        for (int rep = 0; rep < 2; rep++) {
            int f = t + rep * 256;
            if (MODE == 0) {
                int k = f >> 5, n4 = (f & 31) << 2;
                int bn = n0 + n4;
                int ck = ((k >> 2) & 3) << 2;
                cpa16(Bs_ + k * 136 + (n4 ^ ck),
                      W + (size_t)(bn >> 6) * (D_MODEL * DK)
                        + (size_t)(kc * 16 + k) * DK + (bn & 63));
            } else {
                int n = f >> 2, k4 = (f & 3) << 2;
                cpa16(Bs_ + n * A_ROW_STRIDE + k4,
                      W + (size_t)(n0 + n) * D_MODEL + kc * 16 + k4);
            }
        }
    };

    auto compute = [&](int stage) {
        uint32_t* As_ = smA + stage * A_STAGE_WORDS;
        uint32_t* Bs_ = smB + stage * BSTW;
#pragma unroll
        for (int ks = 0; ks < 2; ks++) {
            const int kb = ks * 8;
            uint32_t af[4][4];
#pragma unroll
            for (int mt = 0; mt < 4; mt++) {
                const int r = (wm + mt * 16 + gid) * A_ROW_STRIDE;
                af[mt][0] = As_[r + kb + tig];
                af[mt][1] = As_[r + 8 * A_ROW_STRIDE + kb + tig];
                af[mt][2] = As_[r + kb + tig + 4];
                af[mt][3] = As_[r + 8 * A_ROW_STRIDE + kb + tig + 4];
            }
            uint32_t bf[4][2];
#pragma unroll
            for (int nt = 0; nt < 4; nt++) {
                const int ncol = wn + nt * 8 + gid;
                if (MODE == 0) {
                    const int x0 = ks ? 8 : 0;
                    const int x1 = ks ? 12 : 4;
                    bf[nt][0] = Bs_[(kb + tig) * 136 + (ncol ^ x0)];
                    bf[nt][1] = Bs_[(kb + tig + 4) * 136 + (ncol ^ x1)];
                } else {
                    bf[nt][0] = Bs_[ncol * A_ROW_STRIDE + kb + tig];
                    bf[nt][1] = Bs_[ncol * A_ROW_STRIDE + kb + tig + 4];
                }
            }
#pragma unroll
            for (int mt = 0; mt < 4; mt++)
#pragma unroll
                for (int nt = 0; nt < 4; nt++) mma_tf32(acc[mt][nt], af[mt], bf[nt]);
        }
    };

    issue(0, 0); cpa_commit();
    issue(1, 1); cpa_commit();
    issue(2, 2); cpa_commit();
    for (int kc = 0; kc < 64; kc++) {
        cpa_wait<2>();
        __syncthreads();
        compute(kc & 3);
        if (kc + 3 < 64) issue((kc + 3) & 3, kc + 3);
        cpa_commit();
    }

#pragma unroll
    for (int mt = 0; mt < 4; mt++) {
#pragma unroll
        for (int nt = 0; nt < 4; nt++) {
            const int r0 = m0 + wm + mt * 16 + gid;
            const int r1 = r0 + 8;
            const int c  = n0 + wn + nt * 8 + tig * 2;
            const float bv0 = bias[c], bv1 = bias[c + 1];
            float2 v0 = make_float2(acc[mt][nt][0] + bv0, acc[mt][nt][1] + bv1);
            float2 v1 = make_float2(acc[mt][nt][2] + bv0, acc[mt][nt][3] + bv1);
            *(float2*)(out + (size_t)r0 * D_MODEL + c) = v0;
            *(float2*)(out + (size_t)r1 * D_MODEL + c) = v1;
        }
    }
}

// =====================================================================
// Proj GEMM (R16 core) + fp16 epilogues:
//  z=0 (Q): fp16 [bh][s][d], value*(0.125*log2e), half2 stores
//  z=1 (K): fp16 [bh][s][d], half2 stores
//  z=2 (V): fp16 TRANSPOSED [bh][d][s], 4 scalar half stores
// =====================================================================
struct ProjArgs {
    const float* X[3];
    const float* W[3];
    const float* bias[3];
    __half* out[3];
};

__global__ __launch_bounds__(256, 2) void proj_gemm3_v3_kernel(ProjArgs args)
{
    extern __shared__ uint32_t sg[];
    const int z = blockIdx.z;
    const float* X    = args.X[z];
    const float* W    = args.W[z];
    const float* bias = args.bias[z];
    __half* out       = args.out[z];
    const float escale = (z == 0) ? (0.125f * 1.4426950408889634f) : 1.0f;

    uint32_t* smA = sg;
    uint32_t* smB = sg + NSTAGE * A_STAGE_WORDS;

    const int t    = threadIdx.x;
    const int n0   = blockIdx.x * 128;
    const int m0   = blockIdx.y * 128;
    const int warp = t >> 5;
    const int lane = t & 31;
    const int gid  = lane >> 2;
    const int tig  = lane & 3;
    const int wm   = (warp & 1) * 64;
    const int wn   = (warp >> 1) * 32;

    const int am[2] = { (t + 0) >> 2, (t + 256) >> 2 };
    const int ak4   = (t & 3) << 2;

    float acc[4][4][4];
#pragma unroll
    for (int i = 0; i < 4; i++)
#pragma unroll
        for (int j = 0; j < 4; j++)
#pragma unroll
            for (int k = 0; k < 4; k++) acc[i][j][k] = 0.f;

    auto issue = [&](int stage, int kc) {
        uint32_t* As_ = smA + stage * A_STAGE_WORDS;
        uint32_t* Bs_ = smB + stage * B0_STAGE_WORDS;
#pragma unroll
        for (int rep = 0; rep < 2; rep++) {
            int m = am[rep];
            cpa16(As_ + m * A_ROW_STRIDE + ak4,
                  X + (size_t)(m0 + m) * D_MODEL + kc * 16 + ak4);
        }
#pragma unroll
        for (int rep = 0; rep < 2; rep++) {
            int f = t + rep * 256;
            int k = f >> 5, n4 = (f & 31) << 2;
            int bn = n0 + n4;
            int ck = ((k >> 2) & 3) << 2;
            cpa16(Bs_ + k * 136 + (n4 ^ ck),
                  W + (size_t)(bn >> 6) * (D_MODEL * DK)
                    + (size_t)(kc * 16 + k) * DK + (bn & 63));
        }
    };

    auto compute = [&](int stage) {
        uint32_t* As_ = smA + stage * A_STAGE_WORDS;
        uint32_t* Bs_ = smB + stage * B0_STAGE_WORDS;
#pragma unroll
        for (int ks = 0; ks < 2; ks++) {
            const int kb = ks * 8;
            const int x0 = ks ? 8 : 0;
            const int x1 = ks ? 12 : 4;
            uint32_t af[4][4];
#pragma unroll
            for (int mt = 0; mt < 4; mt++) {
                const int r = (wm + mt * 16 + gid) * A_ROW_STRIDE;
                af[mt][0] = As_[r + kb + tig];
                af[mt][1] = As_[r + 8 * A_ROW_STRIDE + kb + tig];
                af[mt][2] = As_[r + kb + tig + 4];
                af[mt][3] = As_[r + 8 * A_ROW_STRIDE + kb + tig + 4];
            }
            uint32_t bf[4][2];
#pragma unroll
            for (int nt = 0; nt < 4; nt++) {
                const int ncol = wn + nt * 8 + gid;
                bf[nt][0] = Bs_[(kb + tig) * 136 + (ncol ^ x0)];
                bf[nt][1] = Bs_[(kb + tig + 4) * 136 + (ncol ^ x1)];
            }
#pragma unroll
            for (int mt = 0; mt < 4; mt++)
#pragma unroll
                for (int nt = 0; nt < 4; nt++) mma_tf32(acc[mt][nt], af[mt], bf[nt]);
        }
    };

    issue(0, 0); cpa_commit();
    issue(1, 1); cpa_commit();
    issue(2, 2); cpa_commit();
    for (int kc = 0; kc < 64; kc++) {
        cpa_wait<2>();
        __syncthreads();
        compute(kc & 3);
        if (kc + 3 < 64) issue((kc + 3) & 3, kc + 3);
        cpa_commit();
    }

#pragma unroll
    for (int mt = 0; mt < 4; mt++) {
#pragma unroll
        for (int nt = 0; nt < 4; nt++) {
            const int r0 = m0 + wm + mt * 16 + gid;
            const int r1 = r0 + 8;
            const int c  = n0 + wn + nt * 8 + tig * 2;
            const float bv0 = bias[c], bv1 = bias[c + 1];
            float va = (acc[mt][nt][0] + bv0) * escale;
            float vb = (acc[mt][nt][1] + bv1) * escale;
            float vc = (acc[mt][nt][2] + bv0) * escale;
            float vd = (acc[mt][nt][3] + bv1) * escale;
            const int h = c >> 6, kd = c & 63;
            const int b0_ = r0 >> 11, s0 = r0 & 2047;
            const int b1_ = r1 >> 11, s1 = r1 & 2047;
            const int bh0 = b0_ * NUM_HEADS + h;
            const int bh1 = b1_ * NUM_HEADS + h;
            if (z < 2) {
                __half2 h0 = __floats2half2_rn(va, vb);
                __half2 h1 = __floats2half2_rn(vc, vd);
                *(__half2*)(out + ((size_t)bh0 * SEQ + s0) * DK + kd) = h0;
                *(__half2*)(out + ((size_t)bh1 * SEQ + s1) * DK + kd) = h1;
            } else {
                // V transposed: [bh][d][s]
                out[((size_t)bh0 * DK + kd)     * SEQ + s0] = __float2half_rn(va);
                out[((size_t)bh0 * DK + kd + 1) * SEQ + s0] = __float2half_rn(vb);
                out[((size_t)bh1 * DK + kd)     * SEQ + s1] = __float2half_rn(vc);
                out[((size_t)bh1 * DK + kd + 1) * SEQ + s1] = __float2half_rn(vd);
            }
        }
    }
}

// =====================================================================
// Flash attention fp16 (m16n8k16): Q pre-scaled fp16 in gmem; K fp16
// [s][d]; V fp16 transposed [d][s]. S C-frag packs directly into PV
// A-frag (no permutation). Triple-buffered cp.async, exp2 softmax.
// =====================================================================
__global__ __launch_bounds__(256, 2) void flash_mma_kernel()
{
    extern __shared__ uint32_t smu[];
    uint32_t* KsB = smu;                   // NBUF x [64 kv][36 words]
    uint32_t* VsB = smu + NBUF * FB_WORDS; // NBUF x [64 d][36 words]

    const int t    = threadIdx.x;
    const int warp = t >> 5;
    const int lane = t & 31;
    const int gid  = lane >> 2;
    const int tig  = lane & 3;
    const int q0   = blockIdx.x * 128;
    const int bh   = blockIdx.y;

    const __half* qh = g_q  + (size_t)bh * SEQ * DK;
    const __half* kh = g_k  + (size_t)bh * SEQ * DK;
    const __half* vh = g_vt + (size_t)bh * DK * SEQ;

    const int r0 = q0 + warp * 16 + gid;
    const int r1 = r0 + 8;
    uint32_t qf[4][4];
#pragma unroll
    for (int kk = 0; kk < 4; kk++) {
        qf[kk][0] = *(const uint32_t*)&qh[(size_t)r0 * DK + kk * 16 + 2 * tig];
        qf[kk][1] = *(const uint32_t*)&qh[(size_t)r1 * DK + kk * 16 + 2 * tig];
        qf[kk][2] = *(const uint32_t*)&qh[(size_t)r0 * DK + kk * 16 + 8 + 2 * tig];
        qf[kk][3] = *(const uint32_t*)&qh[(size_t)r1 * DK + kk * 16 + 8 + 2 * tig];
    }

    float m0 = -INFINITY, m1 = -INFINITY, l0 = 0.f, l1 = 0.f;
    float o[8][4];
#pragma unroll
    for (int j = 0; j < 8; j++)
#pragma unroll
        for (int k = 0; k < 4; k++) o[j][k] = 0.f;

    // copy coords: tile = 64 rows x 8 chunks(16B) = 512 chunks per matrix
    const int cr[2] = { t >> 3, (t + 256) >> 3 };
    const int cc[2] = { (t & 7) * 8, ((t + 256) & 7) * 8 };  // half offsets

    auto issue_kv = [&](int buf, int s0) {
        uint32_t* Ks_ = KsB + buf * FB_WORDS;
        uint32_t* Vs_ = VsB + buf * FB_WORDS;
#pragma unroll
        for (int rep = 0; rep < 2; rep++) {
            int r = cr[rep], c = cc[rep];
            cpa16(Ks_ + r * FWR + c / 2, kh + (size_t)(s0 + r) * DK + c);
            cpa16(Vs_ + r * FWR + c / 2, vh + (size_t)r * SEQ + s0 + c);
        }
        cpa_commit();
    };

    const int NT = SEQ / 64;  // 32
    issue_kv(0, 0);
    issue_kv(1, 64);

    for (int tile = 0; tile < NT; tile++) {
        const int buf = tile % NBUF;
        uint32_t* Ks = KsB + buf * FB_WORDS;
        uint32_t* Vs = VsB + buf * FB_WORDS;

        cpa_wait<1>();
        __syncthreads();
        if (tile + 2 < NT) issue_kv((tile + 2) % NBUF, (tile + 2) * 64);
        else cpa_commit();   // empty tail group keeps drain order

        // ---- S' = Q' K^T : 4 k-steps x 8 n-tiles ----
        float sacc[8][4];
#pragma unroll
        for (int j = 0; j < 8; j++)
#pragma unroll
            for (int k = 0; k < 4; k++) sacc[j][k] = 0.f;
#pragma unroll
        for (int kk = 0; kk < 4; kk++) {
#pragma unroll
            for (int j = 0; j < 8; j++) {
                uint32_t b0 = Ks[(j * 8 + gid) * FWR + kk * 8 + tig];
                uint32_t b1 = Ks[(j * 8 + gid) * FWR + kk * 8 + 4 + tig];
                mma_f16(sacc[j], qf[kk], b0, b1);
            }
        }

        // ---- fragment-resident online softmax (log2 domain) ----
        float t0 = -INFINITY, t1 = -INFINITY;
#pragma unroll
        for (int j = 0; j < 8; j++) {
            t0 = fmaxf(t0, fmaxf(sacc[j][0], sacc[j][1]));
            t1 = fmaxf(t1, fmaxf(sacc[j][2], sacc[j][3]));
        }
        t0 = fmaxf(t0, __shfl_xor_sync(0xffffffffu, t0, 1));
        t0 = fmaxf(t0, __shfl_xor_sync(0xffffffffu, t0, 2));
        t1 = fmaxf(t1, __shfl_xor_sync(0xffffffffu, t1, 1));
        t1 = fmaxf(t1, __shfl_xor_sync(0xffffffffu, t1, 2));

        float nm0 = fmaxf(m0, t0), nm1 = fmaxf(m1, t1);
        float a0 = exp2f(m0 - nm0), a1 = exp2f(m1 - nm1);
        m0 = nm0; m1 = nm1;

        float p0 = 0.f, p1 = 0.f;
        uint32_t pj0[8], pj1[8];
#pragma unroll
        for (int j = 0; j < 8; j++) {
            float e0 = exp2f(sacc[j][0] - nm0);
            float e1 = exp2f(sacc[j][1] - nm0);
            float e2 = exp2f(sacc[j][2] - nm1);
            float e3 = exp2f(sacc[j][3] - nm1);
            p0 += e0 + e1;
            p1 += e2 + e3;
            pj0[j] = packh2(e0, e1);   // row r0, kv pair
            pj1[j] = packh2(e2, e3);   // row r1, kv pair
        }
        p0 += __shfl_xor_sync(0xffffffffu, p0, 1);
        p0 += __shfl_xor_sync(0xffffffffu, p0, 2);
        p1 += __shfl_xor_sync(0xffffffffu, p1, 1);
        p1 += __shfl_xor_sync(0xffffffffu, p1, 2);
        l0 = l0 * a0 + p0;
        l1 = l1 * a1 + p1;

#pragma unroll
        for (int j = 0; j < 8; j++) {
            o[j][0] *= a0; o[j][1] *= a0;
            o[j][2] *= a1; o[j][3] *= a1;
        }

        // ---- O += P V : 4 kv-k-steps x 8 d-tiles ----
#pragma unroll
        for (int kk = 0; kk < 4; kk++) {
            uint32_t af[4];
            af[0] = pj0[2 * kk];       // (r0, kv 16kk+2tig,+1)
            af[1] = pj1[2 * kk];       // (r1, same)
            af[2] = pj0[2 * kk + 1];   // (r0, kv+8)
            af[3] = pj1[2 * kk + 1];   // (r1, kv+8)
#pragma unroll
            for (int j = 0; j < 8; j++) {
                uint32_t b0 = Vs[(j * 8 + gid) * FWR + kk * 8 + tig];
                uint32_t b1 = Vs[(j * 8 + gid) * FWR + kk * 8 + 4 + tig];
                mma_f16(o[j], af, b0, b1);
            }
        }
    }

    const float i0 = 1.f / l0, i1 = 1.f / l1;
    const int b_ = bh >> 4, h = bh & 15;
    float* row0 = g_cat + (size_t)(b_ * SEQ + r0) * D_MODEL + h * DK;
    float* row1 = g_cat + (size_t)(b_ * SEQ + r1) * D_MODEL + h * DK;
#pragma unroll
    for (int j = 0; j < 8; j++) {
        *(float2*)(row0 + j * 8 + tig * 2) = make_float2(o[j][0] * i0, o[j][1] * i0);
        *(float2*)(row1 + j * 8 + tig * 2) = make_float2(o[j][2] * i1, o[j][3] * i1);
    }
}

extern "C" void kernel_launch(void* const* d_in, const int* in_sizes, int n_in,
                              void* d_out, int out_size)
{
    const float* Q  = (const float*)d_in[0];
    const float* K  = (const float*)d_in[1];
    const float* V  = (const float*)d_in[2];
    const float* Wq = (const float*)d_in[3];
    const float* bq = (const float*)d_in[4];
    const float* Wk = (const float*)d_in[5];
    const float* bk = (const float*)d_in[6];
    const float* Wv = (const float*)d_in[7];
    const float* bv = (const float*)d_in[8];
    const float* Wo = (const float*)d_in[9];
    const float* bo = (const float*)d_in[10];
    float* out = (float*)d_out;

    __half *gq, *gk, *gvt;
    float *gcat;
    cudaGetSymbolAddress((void**)&gq, g_q);
    cudaGetSymbolAddress((void**)&gk, g_k);
    cudaGetSymbolAddress((void**)&gvt, g_vt);
    cudaGetSymbolAddress((void**)&gcat, g_cat);

    const int proj_smem  = (NSTAGE * A_STAGE_WORDS + NSTAGE * B0_STAGE_WORDS) * 4; // 75776
    const int outg_smem  = (NSTAGE * A_STAGE_WORDS + NSTAGE * B1_STAGE_WORDS) * 4; // 81920
    const int flash_smem = NBUF * 2 * FB_WORDS * 4;                                // 55296

    cudaFuncSetAttribute(proj_gemm3_v3_kernel,
                         cudaFuncAttributeMaxDynamicSharedMemorySize, proj_smem);
    cudaFuncSetAttribute(gemm_v3_kernel<1>,
                         cudaFuncAttributeMaxDynamicSharedMemorySize, outg_smem);
    cudaFuncSetAttribute(flash_mma_kernel,
                         cudaFuncAttributeMaxDynamicSharedMemorySize, flash_smem);

    ProjArgs pa;
    pa.X[0] = Q;  pa.X[1] = K;  pa.X[2] = V;
    pa.W[0] = Wq; pa.W[1] = Wk; pa.W[2] = Wv;
    pa.bias[0] = bq; pa.bias[1] = bk; pa.bias[2] = bv;
    pa.out[0] = gq; pa.out[1] = gk; pa.out[2] = gvt;

    dim3 pgrd(D_MODEL / 128, M_TOTAL / 128, 3);
    proj_gemm3_v3_kernel<<<pgrd, dim3(256), proj_smem>>>(pa);

    dim3 fgrd(SEQ / 128, BATCH * NUM_HEADS);
    flash_mma_kernel<<<fgrd, dim3(256), flash_smem>>>();

    dim3 ogrd(D_MODEL / 128, M_TOTAL / 128);
    gemm_v3_kernel<1><<<ogrd, dim3(256), outg_smem>>>(gcat, Wo, bo, out);
}